// round 13
// baseline (speedup 1.0000x reference)
#include <cuda_runtime.h>

// Multi-scale morphological closing, [4,8,256,256] fp32 -> [4,8,4,256,256].
// closing_s = erosion_s(dilation_s(x)), separable h then v per op.
// SE_s[j] = j^2/(4*t_s), t_s = 4^s, half-width SW_s = 4*2^s, weight se_coef.
// kc = c/(4*t_s) = 4c/SW^2.
//
// Round-13: TRANSPOSED v-pass tile. Session finding: only float4-loaded
// windows stay register-resident (1.5 instr/candidate); scalar LDS always
// compiles to streaming 2.5 instr/candidate (32 regs, R9-R12). So vk stages
// its tile transposed in smem (odd float4 row stride -> conflict-free
// LDS.128) and runs the same dense full-window sym-pair loop as hk.
// Sym-pair identity (bit-exact, rel_err 0.0 since R2):
//   max_j v[x+j]-kc*j^2 = max_d fmaf(-kc, d*d, max(v[x-d], v[x+d]))

namespace {
constexpr int IMGS = 32;     // B*C
constexpr int H    = 256;
constexpr int W    = 256;
constexpr int NPIX = H * W;
constexpr int NTOT = IMGS * NPIX;
constexpr int K    = 8;      // outputs per thread
constexpr int ROWS = 8;      // rows per block, h-pass
}

__device__ float g_t1[4][NTOT];
__device__ float g_t2[4][NTOT];

template<bool MX> __device__ __forceinline__ float mm(float a, float b) {
    return MX ? fmaxf(a, b) : fminf(a, b);
}

// ---------------------------------------------------------------------------
// Horizontal pass (R7 measured-best): block = 256 thr = 8 rows x (32 lanes
// x 8 outputs). Row staged in smem with sentinel halo; full window resident
// via aligned LDS.128; dense sym-pair loop.
// ---------------------------------------------------------------------------
template<int SW, bool MX>
__global__ void __launch_bounds__(256) hk(
    const float* __restrict__ in,
    float* __restrict__ out, long ostr,
    const float* __restrict__ sc)
{
    constexpr int PADW = W + 2 * SW;
    constexpr float BIG = MX ? -1e9f : 1e9f;
    const float kc  = (*sc) * (4.0f / (float)(SW * SW));
    const float kcs = MX ? -kc : kc;

    __shared__ __align__(16) float sm[ROWS][PADW];

    const int img = blockIdx.x >> 5;          // 32 row-blocks per image
    const int rb  = blockIdx.x & 31;
    const float* src = in + (long)img * NPIX + (long)(rb * ROWS) * W;

    #pragma unroll
    for (int i = threadIdx.x; i < ROWS * PADW; i += 256) {
        const int r = i / PADW;
        const int p = i - r * PADW;
        const int x = p - SW;
        sm[r][p] = ((unsigned)x < (unsigned)W) ? src[r * W + x] : BIG;
    }
    __syncthreads();

    const int r    = threadIdx.x >> 5;        // warp per row
    const int lane = threadIdx.x & 31;
    const int x0   = lane * K;

    float wv[2 * SW + K];
    const float4* wp = reinterpret_cast<const float4*>(&sm[r][x0]);
    #pragma unroll
    for (int i = 0; i < (2 * SW + K) / 4; ++i) {
        const float4 v = wp[i];
        wv[4 * i + 0] = v.x; wv[4 * i + 1] = v.y;
        wv[4 * i + 2] = v.z; wv[4 * i + 3] = v.w;
    }

    float acc[K];
    #pragma unroll
    for (int k = 0; k < K; ++k) acc[k] = wv[SW + k];      // d = 0

    #pragma unroll
    for (int d = 1; d <= SW; ++d) {
        const float dd = (float)(d * d);                  // imm
        #pragma unroll
        for (int k = 0; k < K; ++k) {
            const float m = mm<MX>(wv[SW + k - d], wv[SW + k + d]);
            acc[k] = mm<MX>(acc[k], fmaf(kcs, dd, m));
        }
    }

    float* dst = out + (long)img * ostr + (long)(rb * ROWS + r) * W + x0;
    #pragma unroll
    for (int k = 0; k < K; ++k) dst[k] = acc[k];
}

// ---------------------------------------------------------------------------
// Vertical pass (transposed tile): block = 32 cols x 64 output rows.
// Tile staged as smT[col][row] with row stride SRP = SR+4 floats (odd in
// float4 units -> conflict-free LDS.128 window reads). Each thread owns one
// column; full window resident in registers; dense sym-pair loop.
// ---------------------------------------------------------------------------
template<int SW, bool MX>
__global__ void __launch_bounds__(256) vk(
    const float* __restrict__ in,
    float* __restrict__ out, long ostr,
    const float* __restrict__ sc)
{
    constexpr int TR  = 64;                   // output rows per block
    constexpr int TC  = 32;                   // cols per block
    constexpr int SR  = TR + 2 * SW;          // staged rows
    constexpr int SRP = SR + 4;               // padded stride (odd float4)
    constexpr float BIG = MX ? -1e9f : 1e9f;
    const float kc  = (*sc) * (4.0f / (float)(SW * SW));
    const float kcs = MX ? -kc : kc;

    __shared__ __align__(16) float smT[TC][SRP];

    const int img = blockIdx.x >> 5;          // 32 tiles per image
    const int t   = blockIdx.x & 31;          // 8 x-tiles x 4 y-tiles
    const int xt  = (t & 7) * TC;
    const int yt  = (t >> 3) * TR;

    const int lane = threadIdx.x & 31;
    const int rg   = threadIdx.x >> 5;        // warp id = row group

    // stage transposed: read coalesced rows, write smT[col][row]
    const float* src = in + (long)img * NPIX + xt;
    if (yt >= SW && yt + TR + SW <= H) {      // interior: unguarded
        for (int i = threadIdx.x; i < SR * TC; i += 256) {
            const int rr = i >> 5, c = i & 31;
            smT[c][rr] = src[(long)(yt - SW + rr) * W + c];
        }
    } else {
        for (int i = threadIdx.x; i < SR * TC; i += 256) {
            const int rr = i >> 5, c = i & 31;
            const int y = yt - SW + rr;
            smT[c][rr] = ((unsigned)y < (unsigned)H) ? src[(long)y * W + c] : BIG;
        }
    }
    __syncthreads();

    // full window (contiguous in transposed layout) via LDS.128
    float wv[2 * SW + K];
    const float4* wp = reinterpret_cast<const float4*>(&smT[lane][rg * K]);
    #pragma unroll
    for (int i = 0; i < (2 * SW + K) / 4; ++i) {
        const float4 v = wp[i];
        wv[4 * i + 0] = v.x; wv[4 * i + 1] = v.y;
        wv[4 * i + 2] = v.z; wv[4 * i + 3] = v.w;
    }

    float acc[K];
    #pragma unroll
    for (int k = 0; k < K; ++k) acc[k] = wv[SW + k];      // d = 0

    #pragma unroll
    for (int d = 1; d <= SW; ++d) {
        const float dd = (float)(d * d);                  // imm
        #pragma unroll
        for (int k = 0; k < K; ++k) {
            const float m = mm<MX>(wv[SW + k - d], wv[SW + k + d]);
            acc[k] = mm<MX>(acc[k], fmaf(kcs, dd, m));
        }
    }

    float* dst = out + (long)img * ostr + (long)(yt + rg * K) * W + xt + lane;
    #pragma unroll
    for (int k = 0; k < K; ++k) dst[(long)k * W] = acc[k];
}

// ---------------------------------------------------------------------------
template<int SW>
static void run_chain(cudaStream_t st, const float* in_p, float* t1_p,
                      float* t2_p, float* out_p, const float* sc)
{
    const int grid = IMGS * 32;               // 1024 blocks, both passes
    hk<SW, true ><<<grid, 256, 0, st>>>(in_p, t1_p, NPIX, sc);
    vk<SW, true ><<<grid, 256, 0, st>>>(t1_p, t2_p, NPIX, sc);
    hk<SW, false><<<grid, 256, 0, st>>>(t2_p, t1_p, NPIX, sc);
    vk<SW, false><<<grid, 256, 0, st>>>(t1_p, out_p, 4L * NPIX, sc);
}

// exact R3 host-object footprint (proved clean vs the mem checker)
static cudaStream_t g_st[3];
static cudaEvent_t  g_fork, g_join[3];
static bool g_ready = false;

extern "C" void kernel_launch(void* const* d_in, const int* in_sizes, int n_in,
                              void* d_out, int out_size)
{
    const float* in = (const float*)d_in[0];
    const float* sc = (const float*)d_in[1];
    if (n_in >= 2 && in_sizes[0] == 1) {      // defensive: order swap
        in = (const float*)d_in[1];
        sc = (const float*)d_in[0];
    }
    float* out = (float*)d_out;

    if (!g_ready) {
        for (int i = 0; i < 3; ++i)
            cudaStreamCreateWithFlags(&g_st[i], cudaStreamNonBlocking);
        cudaEventCreateWithFlags(&g_fork, cudaEventDisableTiming);
        for (int i = 0; i < 3; ++i)
            cudaEventCreateWithFlags(&g_join[i], cudaEventDisableTiming);
        g_ready = true;
    }

    float (*t1)[NTOT] = nullptr;
    float (*t2)[NTOT] = nullptr;
    cudaGetSymbolAddress((void**)&t1, g_t1);
    cudaGetSymbolAddress((void**)&t2, g_t2);

    cudaEventRecord(g_fork, 0);
    for (int i = 0; i < 3; ++i) cudaStreamWaitEvent(g_st[i], g_fork, 0);

    // SW32 (52% of work) on the capture stream; 16/8/4 on side streams
    run_chain<32>(0,       in, t1[3], t2[3], out + 3L * NPIX, sc);
    run_chain<16>(g_st[0], in, t1[2], t2[2], out + 2L * NPIX, sc);
    run_chain< 8>(g_st[1], in, t1[1], t2[1], out + 1L * NPIX, sc);
    run_chain< 4>(g_st[2], in, t1[0], t2[0], out + 0L * NPIX, sc);

    for (int i = 0; i < 3; ++i) {
        cudaEventRecord(g_join[i], g_st[i]);
        cudaStreamWaitEvent(0, g_join[i], 0);
    }

    (void)out_size;
}

// round 14
// speedup vs baseline: 1.0093x; 1.0093x over previous
#include <cuda_runtime.h>

// Multi-scale morphological closing, [4,8,256,256] fp32 -> [4,8,4,256,256].
// closing_s = erosion_s(dilation_s(x)), separable h then v per op.
// SE_s[j] = j^2/(4*t_s), t_s = 4^s, half-width SW_s = 4*2^s, weight se_coef.
// kc = c/(4*t_s) = 4c/SW^2.
//
// Round-14: vk DELETED. All four stages are the measured-best hk kernel;
// each stage writes its output TRANSPOSED via an in-block smem transpose,
// so stage2/stage4 (h-pass on transposed data) are exactly v-dil/v-ero.
//   stage1 h-dil  (normal -> T)      stage2 h-dil on T  == v-dil  (-> N)
//   stage3 h-ero  (N -> T)           stage4 h-ero on T  == v-ero  (-> N, out)
// Sym-pair identity (bit-exact, rel_err 0.0 since R2):
//   max_j v[x+j]-kc*j^2 = max_d fmaf(-kc, d*d, max(v[x-d], v[x+d]))

namespace {
constexpr int IMGS = 32;     // B*C
constexpr int H    = 256;    // square image: transpose-friendly
constexpr int W    = 256;
constexpr int NPIX = H * W;
constexpr int NTOT = IMGS * NPIX;
constexpr int K    = 8;      // outputs per thread
constexpr int ROWS = 8;      // rows per block
}

__device__ float g_t1[4][NTOT];
__device__ float g_t2[4][NTOT];

template<bool MX> __device__ __forceinline__ float mm(float a, float b) {
    return MX ? fmaxf(a, b) : fminf(a, b);
}

// ---------------------------------------------------------------------------
// hk_t: horizontal weighted-max pass with TRANSPOSED output.
// block = 256 thr = 8 rows x (32 lanes x 8 outputs).
// 1) stage 8 rows (+ sentinel halo) in smem
// 2) full window -> registers via aligned LDS.128 (resident form, R3-proven)
// 3) dense symmetric-pair loop
// 4) in-block transpose: acc -> sm (STS.128), reload by column (LDS),
//    write transposed rows as 2x STG.128
// out layout: out_T[x][y] = result[y][x]; per-image stride `ostr`.
// ---------------------------------------------------------------------------
template<int SW, bool MX>
__global__ void __launch_bounds__(256) hk_t(
    const float* __restrict__ in,
    float* __restrict__ out, long ostr,
    const float* __restrict__ sc)
{
    constexpr int PADW = W + 2 * SW;
    constexpr float BIG = MX ? -1e9f : 1e9f;
    const float kc  = (*sc) * (4.0f / (float)(SW * SW));
    const float kcs = MX ? -kc : kc;

    __shared__ __align__(16) float sm[ROWS][PADW];

    const int img = blockIdx.x >> 5;          // 32 row-blocks per image
    const int rb  = blockIdx.x & 31;
    const float* src = in + (long)img * NPIX + (long)(rb * ROWS) * W;

    #pragma unroll
    for (int i = threadIdx.x; i < ROWS * PADW; i += 256) {
        const int r = i / PADW;
        const int p = i - r * PADW;
        const int x = p - SW;
        sm[r][p] = ((unsigned)x < (unsigned)W) ? src[r * W + x] : BIG;
    }
    __syncthreads();

    const int r    = threadIdx.x >> 5;        // warp per row
    const int lane = threadIdx.x & 31;
    const int x0   = lane * K;

    // full window resident (R3-proven geometry)
    float wv[2 * SW + K];
    const float4* wp = reinterpret_cast<const float4*>(&sm[r][x0]);
    #pragma unroll
    for (int i = 0; i < (2 * SW + K) / 4; ++i) {
        const float4 v = wp[i];
        wv[4 * i + 0] = v.x; wv[4 * i + 1] = v.y;
        wv[4 * i + 2] = v.z; wv[4 * i + 3] = v.w;
    }

    float acc[K];
    #pragma unroll
    for (int k = 0; k < K; ++k) acc[k] = wv[SW + k];      // d = 0

    #pragma unroll
    for (int d = 1; d <= SW; ++d) {
        const float dd = (float)(d * d);                  // imm
        #pragma unroll
        for (int k = 0; k < K; ++k) {
            const float m = mm<MX>(wv[SW + k - d], wv[SW + k + d]);
            acc[k] = mm<MX>(acc[k], fmaf(kcs, dd, m));
        }
    }

    // ---- in-block transpose ----
    __syncthreads();                          // input values no longer needed
    {
        float4* q = reinterpret_cast<float4*>(&sm[r][x0]);
        q[0] = make_float4(acc[0], acc[1], acc[2], acc[3]);
        q[1] = make_float4(acc[4], acc[5], acc[6], acc[7]);
    }
    __syncthreads();

    const int tx = threadIdx.x;               // transposed-output row = x
    float o[ROWS];
    #pragma unroll
    for (int rr = 0; rr < ROWS; ++rr) o[rr] = sm[rr][tx];   // conflict-free

    // out_T[x][y], y = rb*ROWS .. +7 contiguous
    float* dst = out + (long)img * ostr + (long)tx * H + rb * ROWS;
    *reinterpret_cast<float4*>(dst)     = make_float4(o[0], o[1], o[2], o[3]);
    *reinterpret_cast<float4*>(dst + 4) = make_float4(o[4], o[5], o[6], o[7]);
}

// ---------------------------------------------------------------------------
// Chain per scale: 4 hk_t stages. Orientation: N -> T -> N -> T -> N.
// ---------------------------------------------------------------------------
template<int SW>
static void run_chain(cudaStream_t st, const float* in_p, float* t1_p,
                      float* t2_p, float* out_p, const float* sc)
{
    const int grid = IMGS * 32;               // 1024 blocks
    hk_t<SW, true ><<<grid, 256, 0, st>>>(in_p, t1_p, NPIX, sc);  // h-dil  -> T
    hk_t<SW, true ><<<grid, 256, 0, st>>>(t1_p, t2_p, NPIX, sc);  // v-dil  -> N
    hk_t<SW, false><<<grid, 256, 0, st>>>(t2_p, t1_p, NPIX, sc);  // h-ero  -> T
    hk_t<SW, false><<<grid, 256, 0, st>>>(t1_p, out_p, 4L * NPIX, sc); // v-ero -> N (slice)
}

// exact R3 host-object footprint (proved clean vs the mem checker)
static cudaStream_t g_st[3];
static cudaEvent_t  g_fork, g_join[3];
static bool g_ready = false;

extern "C" void kernel_launch(void* const* d_in, const int* in_sizes, int n_in,
                              void* d_out, int out_size)
{
    const float* in = (const float*)d_in[0];
    const float* sc = (const float*)d_in[1];
    if (n_in >= 2 && in_sizes[0] == 1) {      // defensive: order swap
        in = (const float*)d_in[1];
        sc = (const float*)d_in[0];
    }
    float* out = (float*)d_out;

    if (!g_ready) {
        for (int i = 0; i < 3; ++i)
            cudaStreamCreateWithFlags(&g_st[i], cudaStreamNonBlocking);
        cudaEventCreateWithFlags(&g_fork, cudaEventDisableTiming);
        for (int i = 0; i < 3; ++i)
            cudaEventCreateWithFlags(&g_join[i], cudaEventDisableTiming);
        g_ready = true;
    }

    float (*t1)[NTOT] = nullptr;
    float (*t2)[NTOT] = nullptr;
    cudaGetSymbolAddress((void**)&t1, g_t1);
    cudaGetSymbolAddress((void**)&t2, g_t2);

    cudaEventRecord(g_fork, 0);
    for (int i = 0; i < 3; ++i) cudaStreamWaitEvent(g_st[i], g_fork, 0);

    // SW32 (52% of work) on the capture stream; 16/8/4 on side streams
    run_chain<32>(0,       in, t1[3], t2[3], out + 3L * NPIX, sc);
    run_chain<16>(g_st[0], in, t1[2], t2[2], out + 2L * NPIX, sc);
    run_chain< 8>(g_st[1], in, t1[1], t2[1], out + 1L * NPIX, sc);
    run_chain< 4>(g_st[2], in, t1[0], t2[0], out + 0L * NPIX, sc);

    for (int i = 0; i < 3; ++i) {
        cudaEventRecord(g_join[i], g_st[i]);
        cudaStreamWaitEvent(0, g_join[i], 0);
    }

    (void)out_size;
}

// round 15
// speedup vs baseline: 1.0996x; 1.0895x over previous
#include <cuda_runtime.h>

// Multi-scale morphological closing, [4,8,256,256] fp32 -> [4,8,4,256,256].
// closing_s = erosion_s(dilation_s(x)), separable h then v per op.
// SE_s[j] = j^2/(4*t_s), t_s = 4^s, half-width SW_s = 4*2^s, weight se_coef.
// kc = c/(4*t_s) = 4c/SW^2.
//
// Round-15: EXACT CASCADE decomposition (Shih-Mitchell). The truncated
// parabolic dilation equals SW successive 3-tap dilations with penalties
// a_d = (2d-1)*kc (a path to offset j uses the |j| cheapest steps:
// sum_{i<=|j|}(2i-1)kc = kc*j^2; staying put is free; |j|>SW unreachable).
// 3 arith/pixel/iteration vs streaming sym-pair's ~5 -> 40% fewer issued
// instructions, no smem in the main loop (row = 1 warp, neighbors via shfl).
// All 4 stages are one kernel with transposed output (R14 transpose tail):
//   N ->(h-dil)-> T ->(v-dil)-> N ->(h-ero)-> T ->(v-ero)-> N(out slice).
// Rounding differs from the single-fmaf reference by <= SW ulps (~1e-6 rel).

namespace {
constexpr int IMGS = 32;     // B*C
constexpr int H    = 256;    // square: transpose-friendly
constexpr int W    = 256;
constexpr int NPIX = H * W;
constexpr int NTOT = IMGS * NPIX;
constexpr int K    = 8;      // pixels per lane (row = 32 lanes * 8 = 256)
constexpr int ROWS = 8;      // rows (warps) per block
}

__device__ float g_t1[4][NTOT];
__device__ float g_t2[4][NTOT];

template<bool MX> __device__ __forceinline__ float mm(float a, float b) {
    return MX ? fmaxf(a, b) : fminf(a, b);
}

// ---------------------------------------------------------------------------
// ck: one cascade pass along rows, transposed output.
// block = 256 thr = 8 warps; warp r owns image row rb*8+r; lane owns 8 px.
// 1) load 8 px/lane straight to registers (2x LDG.128, coalesced)
// 2) SW cascade iterations: 3-tap weighted max/min, neighbors via shfl,
//    image edges clamped to +-1e9 each iteration (exact: removes only
//    suboptimal paths; pad +-10000 never beats the d=0 tap)
// 3) smem transpose, write out_T[x][y] (2x STG.128)
// ---------------------------------------------------------------------------
template<int SW, bool MX>
__global__ void __launch_bounds__(256) ck(
    const float* __restrict__ in,
    float* __restrict__ out, long ostr,
    const float* __restrict__ sc)
{
    constexpr float BIG = MX ? -1e9f : 1e9f;
    const float kc  = (*sc) * (4.0f / (float)(SW * SW));
    const float kcs = MX ? -kc : kc;         // cand = fmaf(kcs, 2d-1, pair)

    const int img  = blockIdx.x >> 5;        // 32 row-blocks per image
    const int rb   = blockIdx.x & 31;
    const int r    = threadIdx.x >> 5;       // warp = row within block
    const int lane = threadIdx.x & 31;
    const int x0   = lane * K;

    // load 8 pixels into registers (coalesced)
    float v[K];
    {
        const float4* src = reinterpret_cast<const float4*>(
            in + (long)img * NPIX + (long)(rb * ROWS + r) * W + x0);
        const float4 a = src[0], b = src[1];
        v[0] = a.x; v[1] = a.y; v[2] = a.z; v[3] = a.w;
        v[4] = b.x; v[5] = b.y; v[6] = b.z; v[7] = b.w;
    }

    // cascade: d = 1..SW, penalty (2d-1)*kc
    #pragma unroll
    for (int d = 1; d <= SW; ++d) {
        float vl = __shfl_up_sync  (0xffffffffu, v[K - 1], 1);
        float vr = __shfl_down_sync(0xffffffffu, v[0],     1);
        if (lane == 0)  vl = BIG;            // image left edge
        if (lane == 31) vr = BIG;            // image right edge
        const float pen = (float)(2 * d - 1);   // imm

        float prev = vl;                     // old v[k-1]
        #pragma unroll
        for (int k = 0; k < K; ++k) {
            const float nxt  = (k < K - 1) ? v[k + 1] : vr;   // old v[k+1]
            const float pair = mm<MX>(prev, nxt);
            const float cand = fmaf(kcs, pen, pair);
            prev = v[k];                     // save old v[k]
            v[k] = mm<MX>(v[k], cand);
        }
    }

    // ---- in-block transpose + coherent write ----
    __shared__ __align__(16) float sm[ROWS][W];
    {
        float4* q = reinterpret_cast<float4*>(&sm[r][x0]);
        q[0] = make_float4(v[0], v[1], v[2], v[3]);
        q[1] = make_float4(v[4], v[5], v[6], v[7]);
    }
    __syncthreads();

    const int tx = threadIdx.x;              // transposed-output row = x
    float o[ROWS];
    #pragma unroll
    for (int rr = 0; rr < ROWS; ++rr) o[rr] = sm[rr][tx];   // conflict-free

    // out_T[x][y], y = rb*8 .. +7 contiguous
    float* dst = out + (long)img * ostr + (long)tx * H + rb * ROWS;
    *reinterpret_cast<float4*>(dst)     = make_float4(o[0], o[1], o[2], o[3]);
    *reinterpret_cast<float4*>(dst + 4) = make_float4(o[4], o[5], o[6], o[7]);
}

// ---------------------------------------------------------------------------
// Chain per scale: 4 ck stages (orientation N->T->N->T->N).
// ---------------------------------------------------------------------------
template<int SW>
static void run_chain(cudaStream_t st, const float* in_p, float* t1_p,
                      float* t2_p, float* out_p, const float* sc)
{
    const int grid = IMGS * 32;              // 1024 blocks
    ck<SW, true ><<<grid, 256, 0, st>>>(in_p, t1_p, NPIX, sc);       // h-dil -> T
    ck<SW, true ><<<grid, 256, 0, st>>>(t1_p, t2_p, NPIX, sc);       // v-dil -> N
    ck<SW, false><<<grid, 256, 0, st>>>(t2_p, t1_p, NPIX, sc);       // h-ero -> T
    ck<SW, false><<<grid, 256, 0, st>>>(t1_p, out_p, 4L * NPIX, sc); // v-ero -> N
}

// exact R3 host-object footprint (proved clean vs the mem checker)
static cudaStream_t g_st[3];
static cudaEvent_t  g_fork, g_join[3];
static bool g_ready = false;

extern "C" void kernel_launch(void* const* d_in, const int* in_sizes, int n_in,
                              void* d_out, int out_size)
{
    const float* in = (const float*)d_in[0];
    const float* sc = (const float*)d_in[1];
    if (n_in >= 2 && in_sizes[0] == 1) {     // defensive: order swap
        in = (const float*)d_in[1];
        sc = (const float*)d_in[0];
    }
    float* out = (float*)d_out;

    if (!g_ready) {
        for (int i = 0; i < 3; ++i)
            cudaStreamCreateWithFlags(&g_st[i], cudaStreamNonBlocking);
        cudaEventCreateWithFlags(&g_fork, cudaEventDisableTiming);
        for (int i = 0; i < 3; ++i)
            cudaEventCreateWithFlags(&g_join[i], cudaEventDisableTiming);
        g_ready = true;
    }

    float (*t1)[NTOT] = nullptr;
    float (*t2)[NTOT] = nullptr;
    cudaGetSymbolAddress((void**)&t1, g_t1);
    cudaGetSymbolAddress((void**)&t2, g_t2);

    cudaEventRecord(g_fork, 0);
    for (int i = 0; i < 3; ++i) cudaStreamWaitEvent(g_st[i], g_fork, 0);

    // SW32 (52% of work) on the capture stream; 16/8/4 on side streams
    run_chain<32>(0,       in, t1[3], t2[3], out + 3L * NPIX, sc);
    run_chain<16>(g_st[0], in, t1[2], t2[2], out + 2L * NPIX, sc);
    run_chain< 8>(g_st[1], in, t1[1], t2[1], out + 1L * NPIX, sc);
    run_chain< 4>(g_st[2], in, t1[0], t2[0], out + 0L * NPIX, sc);

    for (int i = 0; i < 3; ++i) {
        cudaEventRecord(g_join[i], g_st[i]);
        cudaStreamWaitEvent(0, g_join[i], 0);
    }

    (void)out_size;
}

// round 16
// speedup vs baseline: 1.1411x; 1.0377x over previous
#include <cuda_runtime.h>

// Multi-scale morphological closing, [4,8,256,256] fp32 -> [4,8,4,256,256].
// closing_s = erosion_s(dilation_s(x)), separable h then v per op.
// SE_s[j] = j^2/(4*t_s), t_s = 4^s, half-width SW_s = 4*2^s, weight se_coef.
// kc = c/(4*t_s) = 4c/SW^2.
//
// Round-16: Q-TAP EXACT CASCADE. R15's 3-tap cascade was correct
// (rel_err 7.5e-11) but latency-bound: SW-deep serial chain with a 26-cyc
// SHFL per link (issue 55.7%). Generalization: steps of width Q with
// penalties q_d(o) = kc*(2Q(d-1)|o| + o^2), |o|<=Q. Exchange argument =>
// optimal path cost is exactly kc*j^2 for |j|<=SW (greedy fills early
// steps; moving a unit earlier changes cost by <= -2). Q=8:
//   SW=32 -> 4 steps, SW=16 -> 2, SW=8/4 -> 1 (pure window, no chain).
// Same instruction count as R15, 8x shallower dependency chain, shuffles
// batched 16-at-a-time (pipelined). 4 stages per scale, each writing
// transposed output (N->T->N->T->N), R3 stream fork-join.

namespace {
constexpr int IMGS = 32;     // B*C
constexpr int H    = 256;    // square: transpose-friendly
constexpr int W    = 256;
constexpr int NPIX = H * W;
constexpr int NTOT = IMGS * NPIX;
constexpr int K    = 8;      // pixels per lane (row = 32 lanes * 8 = 256)
constexpr int ROWS = 8;      // rows (warps) per block
}

__device__ float g_t1[4][NTOT];
__device__ float g_t2[4][NTOT];

template<bool MX> __device__ __forceinline__ float mm(float a, float b) {
    return MX ? fmaxf(a, b) : fminf(a, b);
}

// ---------------------------------------------------------------------------
// ck: one Q-tap cascade pass along rows, transposed output.
// block = 256 thr = 8 warps; warp r owns image row rb*8+r; lane owns 8 px.
// Per step d (1..NST):
//   halo: L[i] = lane-1's v[K-Q+i], R[i] = lane+1's v[i]  (2Q shuffles,
//         batched; image edges clamped to +-1e9 = exact, paths stay inside)
//   for o = 1..Q:  pen = 2Q(d-1)o + o^2   (compile-time int)
//     v[k] = mm(v[k], fmaf(kcs, pen, mm(v_old[k-o], v_old[k+o])))
// ---------------------------------------------------------------------------
template<int SW, bool MX>
__global__ void __launch_bounds__(256) ck(
    const float* __restrict__ in,
    float* __restrict__ out, long ostr,
    const float* __restrict__ sc)
{
    constexpr int Q   = (SW < 8) ? SW : 8;    // step width
    constexpr int NST = SW / Q;               // number of steps
    constexpr float BIG = MX ? -1e9f : 1e9f;
    const float kc  = (*sc) * (4.0f / (float)(SW * SW));
    const float kcs = MX ? -kc : kc;

    const int img  = blockIdx.x >> 5;         // 32 row-blocks per image
    const int rb   = blockIdx.x & 31;
    const int r    = threadIdx.x >> 5;        // warp = row within block
    const int lane = threadIdx.x & 31;
    const int x0   = lane * K;

    // load 8 pixels into registers (coalesced, 2x LDG.128)
    float v[K];
    {
        const float4* src = reinterpret_cast<const float4*>(
            in + (long)img * NPIX + (long)(rb * ROWS + r) * W + x0);
        const float4 a = src[0], b = src[1];
        v[0] = a.x; v[1] = a.y; v[2] = a.z; v[3] = a.w;
        v[4] = b.x; v[5] = b.y; v[6] = b.z; v[7] = b.w;
    }

    #pragma unroll
    for (int d = 1; d <= NST; ++d) {
        // batched halo exchange (independent shuffles, pipelined)
        float L[Q], R[Q];
        #pragma unroll
        for (int i = 0; i < Q; ++i) L[i] = __shfl_up_sync  (0xffffffffu, v[K - Q + i], 1);
        #pragma unroll
        for (int i = 0; i < Q; ++i) R[i] = __shfl_down_sync(0xffffffffu, v[i], 1);
        if (lane == 0) {
            #pragma unroll
            for (int i = 0; i < Q; ++i) L[i] = BIG;       // image left edge
        }
        if (lane == 31) {
            #pragma unroll
            for (int i = 0; i < Q; ++i) R[i] = BIG;       // image right edge
        }

        float vo[K];
        #pragma unroll
        for (int k = 0; k < K; ++k) vo[k] = v[k];

        #pragma unroll
        for (int o = 1; o <= Q; ++o) {
            const float pen = (float)(2 * Q * (d - 1) * o + o * o);  // imm
            #pragma unroll
            for (int k = 0; k < K; ++k) {
                const float lv = (k - o >= 0) ? vo[k - o] : L[Q + k - o];
                const float rv = (k + o <  K) ? vo[k + o] : R[k + o - K];
                const float cand = fmaf(kcs, pen, mm<MX>(lv, rv));
                v[k] = mm<MX>(v[k], cand);
            }
        }
    }

    // ---- in-block transpose + coherent transposed write ----
    __shared__ __align__(16) float sm[ROWS][W];
    {
        float4* q = reinterpret_cast<float4*>(&sm[r][x0]);
        q[0] = make_float4(v[0], v[1], v[2], v[3]);
        q[1] = make_float4(v[4], v[5], v[6], v[7]);
    }
    __syncthreads();

    const int tx = threadIdx.x;               // transposed-output row = x
    float o8[ROWS];
    #pragma unroll
    for (int rr = 0; rr < ROWS; ++rr) o8[rr] = sm[rr][tx];   // conflict-free

    float* dst = out + (long)img * ostr + (long)tx * H + rb * ROWS;
    *reinterpret_cast<float4*>(dst)     = make_float4(o8[0], o8[1], o8[2], o8[3]);
    *reinterpret_cast<float4*>(dst + 4) = make_float4(o8[4], o8[5], o8[6], o8[7]);
}

// ---------------------------------------------------------------------------
// Chain per scale: 4 ck stages (orientation N->T->N->T->N).
// ---------------------------------------------------------------------------
template<int SW>
static void run_chain(cudaStream_t st, const float* in_p, float* t1_p,
                      float* t2_p, float* out_p, const float* sc)
{
    const int grid = IMGS * 32;               // 1024 blocks
    ck<SW, true ><<<grid, 256, 0, st>>>(in_p, t1_p, NPIX, sc);       // h-dil -> T
    ck<SW, true ><<<grid, 256, 0, st>>>(t1_p, t2_p, NPIX, sc);       // v-dil -> N
    ck<SW, false><<<grid, 256, 0, st>>>(t2_p, t1_p, NPIX, sc);       // h-ero -> T
    ck<SW, false><<<grid, 256, 0, st>>>(t1_p, out_p, 4L * NPIX, sc); // v-ero -> N
}

// exact R3 host-object footprint (proved clean vs the mem checker)
static cudaStream_t g_st[3];
static cudaEvent_t  g_fork, g_join[3];
static bool g_ready = false;

extern "C" void kernel_launch(void* const* d_in, const int* in_sizes, int n_in,
                              void* d_out, int out_size)
{
    const float* in = (const float*)d_in[0];
    const float* sc = (const float*)d_in[1];
    if (n_in >= 2 && in_sizes[0] == 1) {      // defensive: order swap
        in = (const float*)d_in[1];
        sc = (const float*)d_in[0];
    }
    float* out = (float*)d_out;

    if (!g_ready) {
        for (int i = 0; i < 3; ++i)
            cudaStreamCreateWithFlags(&g_st[i], cudaStreamNonBlocking);
        cudaEventCreateWithFlags(&g_fork, cudaEventDisableTiming);
        for (int i = 0; i < 3; ++i)
            cudaEventCreateWithFlags(&g_join[i], cudaEventDisableTiming);
        g_ready = true;
    }

    float (*t1)[NTOT] = nullptr;
    float (*t2)[NTOT] = nullptr;
    cudaGetSymbolAddress((void**)&t1, g_t1);
    cudaGetSymbolAddress((void**)&t2, g_t2);

    cudaEventRecord(g_fork, 0);
    for (int i = 0; i < 3; ++i) cudaStreamWaitEvent(g_st[i], g_fork, 0);

    // SW32 (52% of work) on the capture stream; 16/8/4 on side streams
    run_chain<32>(0,       in, t1[3], t2[3], out + 3L * NPIX, sc);
    run_chain<16>(g_st[0], in, t1[2], t2[2], out + 2L * NPIX, sc);
    run_chain< 8>(g_st[1], in, t1[1], t2[1], out + 1L * NPIX, sc);
    run_chain< 4>(g_st[2], in, t1[0], t2[0], out + 0L * NPIX, sc);

    for (int i = 0; i < 3; ++i) {
        cudaEventRecord(g_join[i], g_st[i]);
        cudaStreamWaitEvent(0, g_join[i], 0);
    }

    (void)out_size;
}

// round 17
// speedup vs baseline: 1.1648x; 1.0208x over previous
#include <cuda_runtime.h>

// Multi-scale morphological closing, [4,8,256,256] fp32 -> [4,8,4,256,256].
// closing_s = erosion_s(dilation_s(x)), separable h then v per op.
// SE_s[j] = j^2/(4*t_s), t_s = 4^s, half-width SW_s = 4*2^s, weight se_coef.
// kc = c/(4*t_s) = 4c/SW^2.
//
// Round-17: Q-tap exact cascade (R16, rel_err 0.0) with K=16 px/lane,
// 16 lanes/row: per-pixel SHFL+SEL overhead halves, step copies eliminated
// via ping-pong arrays (o=1 candidate folds into a 3-operand FMNMX init).
// Penalties q_d(o) = kc*(2Q(d-1)|o| + o^2), |o|<=Q -> path cost exactly
// kc*j^2 for |j|<=SW. 4 transposed-output stages per scale
// (N->T->N->T->N), R3 stream fork-join.

namespace {
constexpr int IMGS = 32;     // B*C
constexpr int H    = 256;    // square: transpose-friendly
constexpr int W    = 256;
constexpr int NPIX = H * W;
constexpr int NTOT = IMGS * NPIX;
constexpr int K    = 16;     // pixels per lane (row = 16 lanes * 16)
constexpr int ROWS = 8;      // rows per block (4 warps x 2 rows)
constexpr int THR  = 128;    // threads per block
}

__device__ float g_t1[4][NTOT];
__device__ float g_t2[4][NTOT];

template<bool MX> __device__ __forceinline__ float mm(float a, float b) {
    return MX ? fmaxf(a, b) : fminf(a, b);
}

// ---------------------------------------------------------------------------
// one cascade step: nxt <- 3-term cascade update of cur (Q offsets each way)
// halo: left = lane-1's cur[K-Q..K-1], right = lane+1's cur[0..Q-1]
// (lanes 0/16 left-edge, 15/31 right-edge -> clamp to BIG; rows are
//  16-lane groups inside the warp)
// ---------------------------------------------------------------------------
template<int Q, bool MX, int D>
__device__ __forceinline__ void cstep(
    const float (&cur)[K], float (&nxt)[K],
    float kcs, bool le, bool re, float BIG)
{
    float L[Q], R[Q];
    #pragma unroll
    for (int i = 0; i < Q; ++i) L[i] = __shfl_up_sync  (0xffffffffu, cur[K - Q + i], 1);
    #pragma unroll
    for (int i = 0; i < Q; ++i) R[i] = __shfl_down_sync(0xffffffffu, cur[i], 1);
    if (le) {
        #pragma unroll
        for (int i = 0; i < Q; ++i) L[i] = BIG;
    }
    if (re) {
        #pragma unroll
        for (int i = 0; i < Q; ++i) R[i] = BIG;
    }

    // o = 1 folds the cur[k] init into the first 3-operand FMNMX
    {
        constexpr float p1 = (float)(2 * Q * (D - 1) + 1);
        #pragma unroll
        for (int k = 0; k < K; ++k) {
            const float lv = (k - 1 >= 0) ? cur[k - 1] : L[Q - 1];
            const float rv = (k + 1 <  K) ? cur[k + 1] : R[0];
            nxt[k] = mm<MX>(cur[k], fmaf(kcs, p1, mm<MX>(lv, rv)));
        }
    }
    #pragma unroll
    for (int o = 2; o <= Q; ++o) {
        const float pen = (float)(2 * Q * (D - 1) * o + o * o);   // imm
        #pragma unroll
        for (int k = 0; k < K; ++k) {
            const float lv = (k - o >= 0) ? cur[k - o] : L[Q + k - o];
            const float rv = (k + o <  K) ? cur[k + o] : R[k + o - K];
            nxt[k] = mm<MX>(nxt[k], fmaf(kcs, pen, mm<MX>(lv, rv)));
        }
    }
}

// ---------------------------------------------------------------------------
// ck: one cascade pass along rows, transposed output.
// block = 128 thr = 4 warps; warp w owns rows 2w, 2w+1 (16 lanes each);
// lane owns 16 px (4x LDG.128). NST = SW/Q cascade steps, ping-pong arrays.
// ---------------------------------------------------------------------------
template<int SW, bool MX>
__global__ void __launch_bounds__(THR) ck(
    const float* __restrict__ in,
    float* __restrict__ out, long ostr,
    const float* __restrict__ sc)
{
    constexpr int Q   = (SW < 8) ? SW : 8;
    constexpr int NST = SW / Q;               // 1,1,2,4
    constexpr float BIG = MX ? -1e9f : 1e9f;
    const float kc  = (*sc) * (4.0f / (float)(SW * SW));
    const float kcs = MX ? -kc : kc;

    const int img  = blockIdx.x >> 5;         // 32 row-blocks per image
    const int rb   = blockIdx.x & 31;
    const int w    = threadIdx.x >> 5;        // warp 0..3
    const int lane = threadIdx.x & 31;
    const int rloc = 2 * w + (lane >> 4);     // row within block 0..7
    const int x0   = (lane & 15) * K;
    const bool le  = (lane & 15) == 0;
    const bool re  = (lane & 15) == 15;

    float A[K], B[K];
    {
        const float4* src = reinterpret_cast<const float4*>(
            in + (long)img * NPIX + (long)(rb * ROWS + rloc) * W + x0);
        #pragma unroll
        for (int i = 0; i < K / 4; ++i) {
            const float4 v = src[i];
            A[4*i+0] = v.x; A[4*i+1] = v.y; A[4*i+2] = v.z; A[4*i+3] = v.w;
        }
    }

    // cascade, ping-pong A -> B -> A -> ...
    cstep<Q, MX, 1>(A, B, kcs, le, re, BIG);
    if constexpr (NST >= 2) cstep<Q, MX, 2>(B, A, kcs, le, re, BIG);
    if constexpr (NST >= 3) cstep<Q, MX, 3>(A, B, kcs, le, re, BIG);
    if constexpr (NST >= 4) cstep<Q, MX, 4>(B, A, kcs, le, re, BIG);
    const float* res = (NST % 2 == 1) ? B : A;

    // ---- in-block transpose + transposed write ----
    __shared__ __align__(16) float sm[ROWS][W];
    {
        float4* q = reinterpret_cast<float4*>(&sm[rloc][x0]);
        #pragma unroll
        for (int i = 0; i < K / 4; ++i)
            q[i] = make_float4(res[4*i+0], res[4*i+1], res[4*i+2], res[4*i+3]);
    }
    __syncthreads();

    // thread t handles transposed-output rows (cols) t and t+128: reads
    // sm[rr][c] with consecutive c across threads -> conflict-free
    #pragma unroll
    for (int h = 0; h < 2; ++h) {
        const int c = threadIdx.x + h * THR;
        float o8[ROWS];
        #pragma unroll
        for (int rr = 0; rr < ROWS; ++rr) o8[rr] = sm[rr][c];
        float* dst = out + (long)img * ostr + (long)c * H + rb * ROWS;
        *reinterpret_cast<float4*>(dst)     = make_float4(o8[0], o8[1], o8[2], o8[3]);
        *reinterpret_cast<float4*>(dst + 4) = make_float4(o8[4], o8[5], o8[6], o8[7]);
    }
}

// ---------------------------------------------------------------------------
// Chain per scale: 4 ck stages (orientation N->T->N->T->N).
// ---------------------------------------------------------------------------
template<int SW>
static void run_chain(cudaStream_t st, const float* in_p, float* t1_p,
                      float* t2_p, float* out_p, const float* sc)
{
    const int grid = IMGS * 32;               // 1024 blocks of 128 thr
    ck<SW, true ><<<grid, THR, 0, st>>>(in_p, t1_p, NPIX, sc);       // h-dil -> T
    ck<SW, true ><<<grid, THR, 0, st>>>(t1_p, t2_p, NPIX, sc);       // v-dil -> N
    ck<SW, false><<<grid, THR, 0, st>>>(t2_p, t1_p, NPIX, sc);       // h-ero -> T
    ck<SW, false><<<grid, THR, 0, st>>>(t1_p, out_p, 4L * NPIX, sc); // v-ero -> N
}

// exact R3 host-object footprint (proved clean vs the mem checker)
static cudaStream_t g_st[3];
static cudaEvent_t  g_fork, g_join[3];
static bool g_ready = false;

extern "C" void kernel_launch(void* const* d_in, const int* in_sizes, int n_in,
                              void* d_out, int out_size)
{
    const float* in = (const float*)d_in[0];
    const float* sc = (const float*)d_in[1];
    if (n_in >= 2 && in_sizes[0] == 1) {      // defensive: order swap
        in = (const float*)d_in[1];
        sc = (const float*)d_in[0];
    }
    float* out = (float*)d_out;

    if (!g_ready) {
        for (int i = 0; i < 3; ++i)
            cudaStreamCreateWithFlags(&g_st[i], cudaStreamNonBlocking);
        cudaEventCreateWithFlags(&g_fork, cudaEventDisableTiming);
        for (int i = 0; i < 3; ++i)
            cudaEventCreateWithFlags(&g_join[i], cudaEventDisableTiming);
        g_ready = true;
    }

    float (*t1)[NTOT] = nullptr;
    float (*t2)[NTOT] = nullptr;
    cudaGetSymbolAddress((void**)&t1, g_t1);
    cudaGetSymbolAddress((void**)&t2, g_t2);

    cudaEventRecord(g_fork, 0);
    for (int i = 0; i < 3; ++i) cudaStreamWaitEvent(g_st[i], g_fork, 0);

    // SW32 (52% of work) on the capture stream; 16/8/4 on side streams
    run_chain<32>(0,       in, t1[3], t2[3], out + 3L * NPIX, sc);
    run_chain<16>(g_st[0], in, t1[2], t2[2], out + 2L * NPIX, sc);
    run_chain< 8>(g_st[1], in, t1[1], t2[1], out + 1L * NPIX, sc);
    run_chain< 4>(g_st[2], in, t1[0], t2[0], out + 0L * NPIX, sc);

    for (int i = 0; i < 3; ++i) {
        cudaEventRecord(g_join[i], g_st[i]);
        cudaStreamWaitEvent(0, g_join[i], 0);
    }

    (void)out_size;
}